// round 16
// baseline (speedup 1.0000x reference)
#include <cuda_runtime.h>
#include <cuda_fp16.h>
#include <stdint.h>

#define N_MAX 50000
#define E_MAX 800000
#define DH 64
#define SCAN_B 256
#define NBLK ((N_MAX + SCAN_B - 1) / SCAN_B)   // 196
#define GEMM_BLOCKS ((N_MAX + 63) / 64)        // 782
#define WPAD 72   // padded weight row stride (floats): kills 2-way LDS conflicts

// ---------------- device scratch ---------------------------------------------
__device__ __align__(256) __half g_bufA[N_MAX * DH];  // fp16 features (ping)
__device__ __align__(256) __half g_bufC[N_MAX * DH];  // fp16 features (pong)
__device__ __align__(16)  float g_dis[N_MAX];
__device__ __align__(16)  int   g_cnt[N_MAX];
__device__ __align__(16)  int   g_rowptr[N_MAX + 1];
__device__ __align__(16)  int   g_look[NBLK];         // spin-scan mailbox
__device__ __align__(16)  int   g_slot[E_MAX];        // per-edge slot in its row
__device__ __align__(16)  int2  g_csr[E_MAX];         // (src, dis[src] as int)

__device__ __forceinline__ bool detect64(const int* __restrict__ w) {
    int lane = threadIdx.x & 31;
    return __all_sync(0xffffffffu, w[2 * lane + 1] == 0);
}

// ---------------- packed f32x2 FMA (sm_103a; ptxas never auto-fuses) ----------
#define FFMA2(acc, ab, w) \
    asm("fma.rn.f32x2 %0, %1, %2, %0;" : "+l"(acc) : "l"(ab), "l"(w))
#define PACK_FF(out, lo, hi) \
    asm("mov.b64 %0, {%1, %2};" : "=l"(out) : "f"(lo), "f"(hi))
#define UNPACK_FF(lo, hi, in) \
    asm("mov.b64 {%0, %1}, %2;" : "=f"(lo), "=f"(hi) : "l"(in))

// Copy a 64x64 row-major weight matrix into padded smem:
// Ws[k*WPAD + j + (j>=32 ? 4 : 0)]. 1024 float4s, stores stay 16B-aligned.
__device__ __forceinline__ void load_weights_padded(
    float* __restrict__ Ws, const float* __restrict__ W, int tid)
{
#pragma unroll
    for (int i = tid; i < 1024; i += 256) {
        float4 w4 = ((const float4*)W)[i];
        int k  = i >> 4;
        int j4 = (i & 15) * 4;
        *(float4*)&Ws[k * WPAD + j4 + ((j4 >= 32) ? 4 : 0)] = w4;
    }
}

// ---------------- launch #1: fused layer-0 GEMM + degree histogram -------------
__global__ __launch_bounds__(256) void k_gemm0_hist(
    const float* __restrict__ x, const float* __restrict__ W0,
    const void* __restrict__ ei, int n, int E)
{
    __shared__ float Ws[64 * WPAD];
    int tid = threadIdx.x;

    if (blockIdx.x < GEMM_BLOCKS) {
        load_weights_padded(Ws, W0, tid);
        __syncthreads();

        int node = blockIdx.x * 64 + (tid >> 2);
        int quad = tid & 3;
        if (node >= n) return;

        const ulonglong2* wsp = (const ulonglong2*)
            &Ws[quad * 16 + ((quad >= 2) ? 4 : 0)];
        unsigned long long o2[8];
#pragma unroll
        for (int j = 0; j < 8; j++) o2[j] = 0ull;

        const float4* xr4 = (const float4*)(x + (size_t)node * 64);
        for (int k4 = 0; k4 < 16; k4++) {
            float4 v4 = xr4[k4];
            float vv[4] = {v4.x, v4.y, v4.z, v4.w};
#pragma unroll
            for (int u = 0; u < 4; u++) {
                unsigned long long vp;
                PACK_FF(vp, vv[u], vv[u]);
                const ulonglong2* row = wsp + (size_t)(k4 * 4 + u) * (WPAD / 4);
                ulonglong2 a = row[0], b = row[1], c2 = row[2], d2 = row[3];
                FFMA2(o2[0], vp, a.x);  FFMA2(o2[1], vp, a.y);
                FFMA2(o2[2], vp, b.x);  FFMA2(o2[3], vp, b.y);
                FFMA2(o2[4], vp, c2.x); FFMA2(o2[5], vp, c2.y);
                FFMA2(o2[6], vp, d2.x); FFMA2(o2[7], vp, d2.y);
            }
        }
        half2 h[8];
#pragma unroll
        for (int j = 0; j < 8; j++) {
            float lo, hi;
            UNPACK_FF(lo, hi, o2[j]);
            h[j] = __float22half2_rn(make_float2(lo, hi));
        }
        uint4* op = (uint4*)(g_bufA + (size_t)node * 64 + quad * 16);
        op[0] = *(uint4*)&h[0];
        op[1] = *(uint4*)&h[4];
    } else {
        int b = blockIdx.x - GEMM_BLOCKS;
        bool is64 = detect64((const int*)ei);
        if (b == 0 && tid < NBLK) g_look[tid] = 0;
        int e = b * 256 + tid;
        if (e >= E) return;
        int d;
        if (is64) d = (int)((const long long*)ei)[e + E];
        else      d = ((const int*)ei)[e + E];
        g_slot[e] = atomicAdd(&g_cnt[d], 1);
    }
}

// ---------------- launch #2: single-kernel scan: rowptr, dis -------------------
__global__ __launch_bounds__(SCAN_B) void k_scan(int n, int E) {
    __shared__ int s[SCAN_B];
    int t = threadIdx.x, b = blockIdx.x;
    int i = b * SCAN_B + t;
    int v = (i < n) ? g_cnt[i] : 0;
    s[t] = v;
    __syncthreads();
#pragma unroll
    for (int off = 1; off < SCAN_B; off <<= 1) {
        int add = (t >= off) ? s[t - off] : 0;
        __syncthreads();
        s[t] += add;
        __syncthreads();
    }
    int excl = s[t] - v;
    int btotal = s[SCAN_B - 1];
    if (t == 0) atomicExch(&g_look[b], (1 << 29) | btotal);

    int contrib = 0;
    if (t < b) {
        int w;
        do { w = atomicAdd(&g_look[t], 0); } while (w == 0);
        contrib = w & 0x1FFFFFFF;
    }
    __syncthreads();
    s[t] = contrib;
    __syncthreads();
#pragma unroll
    for (int off = 128; off >= 1; off >>= 1) {
        if (t < off) s[t] += s[t + off];
        __syncthreads();
    }
    int base = s[0];

    if (i < n) {
        g_rowptr[i] = base + excl;
        g_dis[i] = rsqrtf((float)(v + 1));
    }
    if (b == 0 && t == 0) g_rowptr[n] = E;
}

// ---------------- launch #3: CSR fill (atomic-free; packs dis[src]) ------------
__global__ void k_fill(const void* __restrict__ ei, int E) {
    const int* w = (const int*)ei;
    bool is64 = detect64(w);
    int e = blockIdx.x * blockDim.x + threadIdx.x;
    if (e >= E) return;
    int s, d;
    if (is64) {
        const long long* p = (const long long*)ei;
        s = (int)p[e];
        d = (int)p[e + E];
    } else {
        s = w[e];
        d = w[e + E];
    }
    g_csr[g_rowptr[d] + g_slot[e]] = make_int2(s, __float_as_int(g_dis[s]));
}

// ---------------- fp16 helpers --------------------------------------------------
__device__ __forceinline__ void h8acc(uint4 u, float d, float acc[8]) {
    float2 f0 = __half22float2(*(const half2*)&u.x);
    float2 f1 = __half22float2(*(const half2*)&u.y);
    float2 f2 = __half22float2(*(const half2*)&u.z);
    float2 f3 = __half22float2(*(const half2*)&u.w);
    acc[0] = fmaf(f0.x, d, acc[0]); acc[1] = fmaf(f0.y, d, acc[1]);
    acc[2] = fmaf(f1.x, d, acc[2]); acc[3] = fmaf(f1.y, d, acc[3]);
    acc[4] = fmaf(f2.x, d, acc[4]); acc[5] = fmaf(f2.y, d, acc[5]);
    acc[6] = fmaf(f3.x, d, acc[6]); acc[7] = fmaf(f3.y, d, acc[7]);
}

// Gather one node-column: acc = dv*xw[v] + sum_s dis[s]*xw[s], fp32 accum.
__device__ __forceinline__ void gather8(
    const uint4* __restrict__ xa, int node, int c, float dv, float acc[8])
{
    uint4 me = xa[node * 8 + c];
    float2 f0 = __half22float2(*(const half2*)&me.x);
    float2 f1 = __half22float2(*(const half2*)&me.y);
    float2 f2 = __half22float2(*(const half2*)&me.z);
    float2 f3 = __half22float2(*(const half2*)&me.w);
    acc[0] = f0.x * dv; acc[1] = f0.y * dv;
    acc[2] = f1.x * dv; acc[3] = f1.y * dv;
    acc[4] = f2.x * dv; acc[5] = f2.y * dv;
    acc[6] = f3.x * dv; acc[7] = f3.y * dv;

    int p   = g_rowptr[node];
    int end = g_rowptr[node + 1];

    int2 e0, e1, e2, e3;
    if (p + 3 < end) {
        e0 = g_csr[p]; e1 = g_csr[p + 1]; e2 = g_csr[p + 2]; e3 = g_csr[p + 3];
    }
    while (p + 3 < end) {
        uint4 v0 = xa[e0.x * 8 + c];
        uint4 v1 = xa[e1.x * 8 + c];
        uint4 v2 = xa[e2.x * 8 + c];
        uint4 v3 = xa[e3.x * 8 + c];
        float d0 = __int_as_float(e0.y), d1 = __int_as_float(e1.y);
        float d2 = __int_as_float(e2.y), d3 = __int_as_float(e3.y);
        p += 4;
        if (p + 3 < end) {   // prefetch next batch
            e0 = g_csr[p]; e1 = g_csr[p + 1]; e2 = g_csr[p + 2]; e3 = g_csr[p + 3];
        }
        h8acc(v0, d0, acc);
        h8acc(v1, d1, acc);
        h8acc(v2, d2, acc);
        h8acc(v3, d3, acc);
    }
    for (; p < end; p++) {
        int2 e = g_csr[p];
        h8acc(xa[e.x * 8 + c], __int_as_float(e.y), acc);
    }
}

// ---------------- launches #4,#5: fused gather + bias + relu + 64x64 GEMM ------
// Warp owns 4 nodes (8 lanes x 8 cols). Staging holds PRE-DUPLICATED (v,v) u64
// pairs so the GEMM loop is pure LDS.64 + 2x LDS.128 + 4x FFMA2 per k (no PACK,
// no scalar broadcast). 5 resident blocks guaranteed (40 warps/SM).
__global__ __launch_bounds__(256, 5) void k_gather_gemm(
    const __half* __restrict__ fin, __half* __restrict__ fout,
    const float* __restrict__ W, const float* __restrict__ bias_in, int n)
{
    __shared__ float Ws[64 * WPAD];                       // 18 KB
    __shared__ float bs[64];
    __shared__ unsigned long long agg[8][4][68];          // dup (v,v) slabs, 17 KB

    int tid = threadIdx.x;
    load_weights_padded(Ws, W, tid);
    if (tid < 16) ((float4*)bs)[tid] = ((const float4*)bias_in)[tid];
    __syncthreads();

    int w = tid >> 5;
    int g = (tid >> 3) & 3;
    int c = tid & 7;
    int node = blockIdx.x * 32 + (tid >> 3);
    bool ok = node < n;

    if (ok) {
        float dv = g_dis[node];
        float acc[8];
        gather8((const uint4*)fin, node, c, dv, acc);
        unsigned long long* arow = agg[w][g];
#pragma unroll
        for (int i = 0; i < 8; i++) {
            float v = fmaxf(fmaf(acc[i], dv, bs[c * 8 + i]), 0.f);
            unsigned long long vp;
            PACK_FF(vp, v, v);
            arow[c * 8 + i] = vp;
        }
    }
    __syncwarp();

    if (ok) {
        unsigned long long o2[4];
#pragma unroll
        for (int j = 0; j < 4; j++) o2[j] = 0ull;
        const unsigned long long* arow = agg[w][g];
        const ulonglong2* wsp = (const ulonglong2*)
            &Ws[c * 8 + ((c >= 4) ? 4 : 0)];
#pragma unroll 8
        for (int k = 0; k < 64; k++) {
            unsigned long long vp = arow[k];               // LDS.64, 4-way dedup
            ulonglong2 wA = wsp[(size_t)k * (WPAD / 4)];   // LDS.128, 1 phase
            ulonglong2 wB = wsp[(size_t)k * (WPAD / 4) + 1];
            FFMA2(o2[0], vp, wA.x);
            FFMA2(o2[1], vp, wA.y);
            FFMA2(o2[2], vp, wB.x);
            FFMA2(o2[3], vp, wB.y);
        }
        half2 h[4];
#pragma unroll
        for (int j = 0; j < 4; j++) {
            float lo, hi;
            UNPACK_FF(lo, hi, o2[j]);
            h[j] = __float22half2_rn(make_float2(lo, hi));
        }
        *(uint4*)(fout + (size_t)node * 64 + c * 8) = *(uint4*)&h[0];
    }
}

// ---------------- launch #6: fused gather + bias + relu + 64x8 head ------------
__global__ __launch_bounds__(256) void k_gather_final(
    const __half* __restrict__ fin, float* __restrict__ out,
    const float* __restrict__ linW, const float* __restrict__ b2,
    const float* __restrict__ linb, int n)
{
    __shared__ float Ws[64 * 8];
    __shared__ float bs[64];
    __shared__ float lb[8];
    __shared__ float agg[8][4][68];

    int tid = threadIdx.x;
#pragma unroll
    for (int i = tid; i < 128; i += 256) ((float4*)Ws)[i] = ((const float4*)linW)[i];
    if (tid < 16) ((float4*)bs)[tid] = ((const float4*)b2)[tid];
    if (tid < 2)  ((float4*)lb)[tid] = ((const float4*)linb)[tid];
    __syncthreads();

    int w = tid >> 5;
    int g = (tid >> 3) & 3;
    int c = tid & 7;
    int node = blockIdx.x * 32 + (tid >> 3);
    bool ok = node < n;

    if (ok) {
        float dv = g_dis[node];
        float acc[8];
        gather8((const uint4*)fin, node, c, dv, acc);
        float* arow = agg[w][g];
#pragma unroll
        for (int i = 0; i < 8; i++)
            arow[c * 8 + i] = fmaxf(fmaf(acc[i], dv, bs[c * 8 + i]), 0.f);
    }
    __syncwarp();

    if (ok) {
        const float* arow = agg[w][g];
        float o = lb[c];                           // lane c -> output col c
#pragma unroll 8
        for (int k = 0; k < 64; k++)
            o = fmaf(arow[k], Ws[k * 8 + c], o);   // conflict-free (8 banks)
        out[(size_t)node * 8 + c] = o;
    }
}

// ---------------- host launcher ------------------------------------------------
extern "C" void kernel_launch(void* const* d_in, const int* in_sizes, int n_in,
                              void* d_out, int out_size)
{
    const float* x    = (const float*)d_in[0];
    const void*  ei   = d_in[1];
    const float* W0   = (const float*)d_in[2];
    const float* b0   = (const float*)d_in[3];
    const float* W1   = (const float*)d_in[4];
    const float* b1   = (const float*)d_in[5];
    const float* W2   = (const float*)d_in[6];
    const float* b2   = (const float*)d_in[7];
    const float* linW = (const float*)d_in[8];
    const float* linb = (const float*)d_in[9];
    float* out = (float*)d_out;

    int N = in_sizes[0] / DH;       // 50000
    int E = in_sizes[1] / 2;        // 800000

    const int T = 256;
    int gN = (N + T - 1) / T;       // 196
    int gE = (E + T - 1) / T;       // 3125
    int gA = (N + 31) / 32;         // 1563

    static __half* bufA = nullptr;
    static __half* bufC = nullptr;
    static int*    cntP = nullptr;
    if (!bufA) {
        void* p;
        cudaGetSymbolAddress(&p, g_bufA); bufA = (__half*)p;
        cudaGetSymbolAddress(&p, g_bufC); bufC = (__half*)p;
        cudaGetSymbolAddress(&p, g_cnt);  cntP = (int*)p;
    }
    cudaMemsetAsync(cntP, 0, (size_t)N * sizeof(int));

    // #1: fused layer-0 GEMM + histogram (+ per-edge slot)
    k_gemm0_hist<<<GEMM_BLOCKS + gE, T>>>(x, W0, ei, N, E);
    // #2: scan -> rowptr, dis
    k_scan<<<gN, SCAN_B>>>(N, E);
    // #3: CSR fill (no atomics; packs dis[src])
    k_fill<<<gE, T>>>(ei, E);
    // #4: gather0 + relu(b0) + W1 GEMM   <-- ncu capture lands here
    k_gather_gemm<<<gA, T>>>(bufA, bufC, W1, b0, N);
    // #5: gather1 + relu(b1) + W2 GEMM
    k_gather_gemm<<<gA, T>>>(bufC, bufA, W2, b1, N);
    // #6: gather2 + relu(b2) + head
    k_gather_final<<<gA, T>>>(bufA, out, linW, b2, linb, N);
}